// round 14
// baseline (speedup 1.0000x reference)
#include <cuda_runtime.h>
#include <cuda_fp16.h>
#include <cstdint>
#include <cstddef>

// Problem constants
#define NN 100000
#define NPAD 100096   // 1564 * 64
#define EE 400000
#define RR 4
#define NCHUNK 98     // ceil(NN/1024)

// ---------------- scratch (static device globals; no allocation) ----------------
__device__ int   g_deg_in [RR*NN];
__device__ int   g_deg_out[RR*NN];
__device__ int   g_fill   [RR*NN];
__device__ int   g_rowptr [RR*(NN+1)];
__device__ __align__(16) int2 g_csrp[RR*EE];   // packed (src, dsout bits)
__device__ float g_dsin   [RR*NN];
__device__ float g_dsout  [RR*NN];
// y2 fp16
__device__ __align__(16) unsigned short g_y2[(size_t)NN*64];
// fp16 feature tables (gather inputs)
__device__ __align__(16) unsigned short g_x16[(size_t)NN*128];
__device__ __align__(16) unsigned short g_h1 [(size_t)NPAD*128];
// aggregated features, fp16: [R][NPAD][128]  (pad rows stay zero)
__device__ __align__(16) unsigned short g_agg[(size_t)RR*NPAD*128];
// layer-1 output, fp16: [NPAD][128]
__device__ __align__(16) unsigned short g_h2[(size_t)NPAD*128];
// transposed fp16 weights: bt[r][n][k] = W[r][k][n]
__device__ __align__(16) unsigned short g_bt0[RR*128*128];
__device__ __align__(16) unsigned short g_bt1[RR*128*128];
__device__ __align__(16) unsigned short g_bt2[64*128];   // [r*16+n][k]

// ---------------- helpers ----------------
__device__ __forceinline__ uint32_t smem_u32(const void* p) {
    uint32_t a;
    asm("{ .reg .u64 t; cvta.to.shared.u64 t, %1; cvt.u32.u64 %0, t; }" : "=r"(a) : "l"(p));
    return a;
}
__device__ __forceinline__ void ldsm4(uint32_t* r, uint32_t addr) {
    asm volatile("ldmatrix.sync.aligned.m8n8.x4.shared.b16 {%0,%1,%2,%3}, [%4];"
                 : "=r"(r[0]), "=r"(r[1]), "=r"(r[2]), "=r"(r[3]) : "r"(addr));
}
__device__ __forceinline__ void mma16816(float* d, const uint32_t* a, const uint32_t* b) {
    asm volatile("mma.sync.aligned.m16n8k16.row.col.f32.f16.f16.f32 "
                 "{%0,%1,%2,%3}, {%4,%5,%6,%7}, {%8,%9}, {%0,%1,%2,%3};"
                 : "+f"(d[0]), "+f"(d[1]), "+f"(d[2]), "+f"(d[3])
                 : "r"(a[0]), "r"(a[1]), "r"(a[2]), "r"(a[3]), "r"(b[0]), "r"(b[1]));
}
__device__ __forceinline__ void cp16(uint32_t dst, const void* src) {
    asm volatile("cp.async.cg.shared.global [%0], [%1], 16;" :: "r"(dst), "l"(src));
}
#define CP_COMMIT() asm volatile("cp.async.commit_group;" ::: "memory")
#define CP_WAIT(n)  asm volatile("cp.async.wait_group " #n ";" ::: "memory")

__device__ __forceinline__ uint32_t f2h2(float a, float b) {   // pack 2 fp32 -> half2 (a=low)
    __half2 h = __floats2half2_rn(a, b);
    return *reinterpret_cast<uint32_t*>(&h);
}
__device__ __forceinline__ unsigned short f2h(float f) {
    __half h = __float2half_rn(f);
    return *reinterpret_cast<unsigned short*>(&h);
}

// ---------------- prep kernels ----------------
// zero counters + convert all weights + convert x -> fp16 (one fused elementwise pass)
__global__ void prep_cvt_kernel(const float* __restrict__ x,
                                const float* __restrict__ W0, const float* __restrict__ W1,
                                const float* __restrict__ W2) {
    int i = blockIdx.x * blockDim.x + threadIdx.x;
    if (i < RR*NN) { g_deg_in[i] = 0; g_deg_out[i] = 0; g_fill[i] = 0; }
    const int L01 = RR*128*128;   // 65536
    if (i < L01) {
        int r = i >> 14, n = (i >> 7) & 127, k = i & 127;
        g_bt0[i] = f2h(W0[(r<<14) + k*128 + n]);
    } else if (i < 2*L01) {
        int j = i - L01;
        int r = j >> 14, n = (j >> 7) & 127, k = j & 127;
        g_bt1[j] = f2h(W1[(r<<14) + k*128 + n]);
    } else if (i < 2*L01 + 64*128) {
        int j = i - 2*L01;
        int r = j >> 11, n = (j >> 7) & 15, k = j & 127;
        g_bt2[j] = f2h(W2[r*2048 + k*16 + n]);
    }
    if (i < NN*32) {   // one float4 -> one uint2 of half2
        float4 v = reinterpret_cast<const float4*>(x)[i];
        reinterpret_cast<uint2*>(g_x16)[i] = make_uint2(f2h2(v.x, v.y), f2h2(v.z, v.w));
    }
}
__global__ void count_deg_kernel(const int* __restrict__ src, const int* __restrict__ dst) {
    int idx = blockIdx.x * blockDim.x + threadIdx.x;
    if (idx >= RR*EE) return;
    int r = idx / EE;
    atomicAdd(&g_deg_out[r*NN + src[idx]], 1);
    atomicAdd(&g_deg_in [r*NN + dst[idx]], 1);
}
// fused exclusive scan + scales: one persistent block per relation, carried base
__global__ void scan_scales_kernel() {
    __shared__ int wsum[32];
    __shared__ int carry_sh;
    int r = blockIdx.x;
    int lane = threadIdx.x & 31, w = threadIdx.x >> 5;
    if (threadIdx.x == 0) carry_sh = 0;
    __syncthreads();
    for (int c = 0; c < NCHUNK; c++) {
        int i = c*1024 + threadIdx.x;
        int din = (i < NN) ? g_deg_in[r*NN + i] : 0;
        int v = din;
        #pragma unroll
        for (int off = 1; off < 32; off <<= 1) {
            int t = __shfl_up_sync(0xffffffffu, v, off);
            if (lane >= off) v += t;
        }
        if (lane == 31) wsum[w] = v;
        __syncthreads();
        if (w == 0) {
            int s = wsum[lane];
            #pragma unroll
            for (int off = 1; off < 32; off <<= 1) {
                int t = __shfl_up_sync(0xffffffffu, s, off);
                if (lane >= off) s += t;
            }
            wsum[lane] = s;   // inclusive warp-sums
        }
        __syncthreads();
        int base = carry_sh + ((w > 0) ? wsum[w-1] : 0);
        if (i < NN) {
            g_rowptr[r*(NN+1) + i] = base + v - din;   // exclusive
            int ii = r*NN + i;
            g_dsin [ii] = rsqrtf((float)max(din, 1));
            g_dsout[ii] = rsqrtf((float)max(g_deg_out[ii], 1));
        }
        __syncthreads();
        if (threadIdx.x == 0) carry_sh += wsum[31];
        __syncthreads();
    }
    if (threadIdx.x == 0) g_rowptr[r*(NN+1) + NN] = EE;
}
// fill packed CSR: (src, dsout[src]) per edge
__global__ void fill_csr_kernel(const int* __restrict__ src, const int* __restrict__ dst) {
    int idx = blockIdx.x * blockDim.x + threadIdx.x;
    if (idx >= RR*EE) return;
    int r = idx / EE;
    int s = src[idx];
    int d = dst[idx];
    float w = g_dsout[r*NN + s];
    int pos = atomicAdd(&g_fill[r*NN + d], 1);
    g_csrp[r*EE + g_rowptr[r*(NN+1) + d] + pos] = make_int2(s, __float_as_int(w));
}

// ---------------- gather: agg[r][n] = dsin * sum h[s]*dsout[s]  (fp16 in -> fp16 out) ----------------
// 4-way edge batching: load 4 edge descriptors, then 4 independent row loads,
// then FMAs — breaks the serial csrp->row chain without extra instructions.
__global__ __launch_bounds__(256) void gather_kernel(int use_x) {
    int gw   = (blockIdx.x * blockDim.x + threadIdx.x) >> 5;
    int lane = threadIdx.x & 31;
    if (gw >= RR*NN) return;
    int r = gw / NN, n = gw - r*NN;
    const unsigned short* __restrict__ h = use_x ? g_x16 : g_h1;
    int beg = g_rowptr[r*(NN+1) + n];
    int end = g_rowptr[r*(NN+1) + n + 1];
    float4 acc = make_float4(0.f, 0.f, 0.f, 0.f);
    const int2* __restrict__ cp = g_csrp + (size_t)r*EE;
    int e = beg;
    for (; e + 4 <= end; e += 4) {
        int2 p0 = cp[e], p1 = cp[e+1], p2 = cp[e+2], p3 = cp[e+3];
        uint2 q0 = *reinterpret_cast<const uint2*>(&h[(size_t)p0.x*128 + lane*4]);
        uint2 q1 = *reinterpret_cast<const uint2*>(&h[(size_t)p1.x*128 + lane*4]);
        uint2 q2 = *reinterpret_cast<const uint2*>(&h[(size_t)p2.x*128 + lane*4]);
        uint2 q3 = *reinterpret_cast<const uint2*>(&h[(size_t)p3.x*128 + lane*4]);
        float w0 = __int_as_float(p0.y), w1 = __int_as_float(p1.y);
        float w2 = __int_as_float(p2.y), w3 = __int_as_float(p3.y);
        float2 a0 = __half22float2(*reinterpret_cast<__half2*>(&q0.x));
        float2 b0 = __half22float2(*reinterpret_cast<__half2*>(&q0.y));
        acc.x = fmaf(a0.x, w0, acc.x); acc.y = fmaf(a0.y, w0, acc.y);
        acc.z = fmaf(b0.x, w0, acc.z); acc.w = fmaf(b0.y, w0, acc.w);
        float2 a1 = __half22float2(*reinterpret_cast<__half2*>(&q1.x));
        float2 b1 = __half22float2(*reinterpret_cast<__half2*>(&q1.y));
        acc.x = fmaf(a1.x, w1, acc.x); acc.y = fmaf(a1.y, w1, acc.y);
        acc.z = fmaf(b1.x, w1, acc.z); acc.w = fmaf(b1.y, w1, acc.w);
        float2 a2 = __half22float2(*reinterpret_cast<__half2*>(&q2.x));
        float2 b2 = __half22float2(*reinterpret_cast<__half2*>(&q2.y));
        acc.x = fmaf(a2.x, w2, acc.x); acc.y = fmaf(a2.y, w2, acc.y);
        acc.z = fmaf(b2.x, w2, acc.z); acc.w = fmaf(b2.y, w2, acc.w);
        float2 a3 = __half22float2(*reinterpret_cast<__half2*>(&q3.x));
        float2 b3 = __half22float2(*reinterpret_cast<__half2*>(&q3.y));
        acc.x = fmaf(a3.x, w3, acc.x); acc.y = fmaf(a3.y, w3, acc.y);
        acc.z = fmaf(b3.x, w3, acc.z); acc.w = fmaf(b3.y, w3, acc.w);
    }
    for (; e < end; e++) {
        int2 p  = cp[e];
        float w = __int_as_float(p.y);
        uint2 q = *reinterpret_cast<const uint2*>(&h[(size_t)p.x*128 + lane*4]);
        float2 f01 = __half22float2(*reinterpret_cast<__half2*>(&q.x));
        float2 f23 = __half22float2(*reinterpret_cast<__half2*>(&q.y));
        acc.x = fmaf(f01.x, w, acc.x);
        acc.y = fmaf(f01.y, w, acc.y);
        acc.z = fmaf(f23.x, w, acc.z);
        acc.w = fmaf(f23.y, w, acc.w);
    }
    float si = g_dsin[r*NN + n];
    size_t off = ((size_t)r*NPAD + n)*128 + lane*4;
    *reinterpret_cast<uint2*>(&g_agg[off]) =
        make_uint2(f2h2(acc.x*si, acc.y*si), f2h2(acc.z*si, acc.w*si));
}

// ---------------- big-layer GEMM: 64x128 tile, fp16 single-pass, 3-stage ring ----------------
// Stage layout: A[64][40] @0 (5120B), B[128][40] @5120 (10240B). Stage = 15360 B.
#define STAGE_B 15360
#define GEMM_SMEM (3*STAGE_B)   // 46080

template<int LAYER>
__global__ __launch_bounds__(256, 2) void gemm_kernel(const float* __restrict__ bias) {
    constexpr int S = 16;   // 4 relations x 4 K-chunks of 32

    const unsigned short* Bt = (LAYER == 0) ? g_bt0 : g_bt1;
    unsigned short* Hout = (LAYER == 0) ? g_h1 : g_h2;

    extern __shared__ char dsm[];
    const uint32_t smem_base = smem_u32(dsm);

    const int tid  = threadIdx.x;
    const int lane = tid & 31;
    const int wid  = tid >> 5;
    const int m0   = blockIdx.x * 64;

    const int m_w = (wid >> 2) * 32;      // 0 or 32
    const int n_w = (wid & 3) * 32;       // 0..96
    const int a_r = lane & 15;
    const int a_c = (lane >> 4) << 3;
    const int b_q = lane >> 3;
    const int b_n = ((b_q >> 1) << 3) + (lane & 7);
    const int b_c = (b_q & 1) << 3;

    auto load_stage = [&](int s) {
        int r = s >> 2, kc = s & 3;
        uint32_t sb = smem_base + (s % 3) * STAGE_B;
        size_t a_base = ((size_t)r * NPAD + m0) * 128 + kc * 32;
        size_t b_base = (size_t)r * 128 * 128 + kc * 32;
        #pragma unroll
        for (int i = 0; i < 3; i++) {   // 768 chunks of 16B
            int g = tid + i * 256;
            if (g < 256) {              // A: 64 rows x 4 chunks
                int row = g >> 2, ch = g & 3;
                cp16(sb + row * 80 + ch * 16, g_agg + a_base + (size_t)row * 128 + ch * 8);
            } else {                    // B: 128 rows x 4 chunks
                int idx = g - 256, row = idx >> 2, ch = idx & 3;
                cp16(sb + 5120 + row * 80 + ch * 16, Bt + b_base + (size_t)row * 128 + ch * 8);
            }
        }
        CP_COMMIT();
    };

    float acc[2][4][4];
    float sum[2][4][4];
    #pragma unroll
    for (int i = 0; i < 2; i++)
        #pragma unroll
        for (int j = 0; j < 4; j++)
            #pragma unroll
            for (int c = 0; c < 4; c++) { acc[i][j][c] = 0.f; sum[i][j][c] = 0.f; }

    load_stage(0);
    load_stage(1);

    for (int s = 0; s < S; s++) {
        if (s + 1 < S) CP_WAIT(1); else CP_WAIT(0);
        __syncthreads();
        if (s + 2 < S) load_stage(s + 2);

        uint32_t sb = smem_base + (s % 3) * STAGE_B;
        #pragma unroll
        for (int ks = 0; ks < 2; ks++) {
            int k0 = ks * 16;
            uint32_t a[2][4], b[4][2];
            #pragma unroll
            for (int i = 0; i < 2; i++)
                ldsm4(a[i], sb + (uint32_t)((m_w + i*16 + a_r) * 40 + k0 + a_c) * 2);
            #pragma unroll
            for (int jj = 0; jj < 2; jj++) {
                uint32_t tmp[4];
                ldsm4(tmp, sb + 5120 + (uint32_t)((n_w + jj*16 + b_n) * 40 + k0 + b_c) * 2);
                b[jj*2][0] = tmp[0]; b[jj*2][1] = tmp[1];
                b[jj*2+1][0] = tmp[2]; b[jj*2+1][1] = tmp[3];
            }
            #pragma unroll
            for (int i = 0; i < 2; i++)
                #pragma unroll
                for (int j = 0; j < 4; j++)
                    mma16816(acc[i][j], a[i], b[j]);
        }

        if ((s & 3) == 3) {   // relation rr done: bias + relu, fold into sum
            int rr = s >> 2;
            #pragma unroll
            for (int i = 0; i < 2; i++) {
                #pragma unroll
                for (int j = 0; j < 4; j++) {
                    int col = n_w + j*8 + (lane & 3)*2;
                    float b0v = bias[rr*128 + col];
                    float b1v = bias[rr*128 + col + 1];
                    sum[i][j][0] += fmaxf(acc[i][j][0] + b0v, 0.f);
                    sum[i][j][1] += fmaxf(acc[i][j][1] + b1v, 0.f);
                    sum[i][j][2] += fmaxf(acc[i][j][2] + b0v, 0.f);
                    sum[i][j][3] += fmaxf(acc[i][j][3] + b1v, 0.f);
                    acc[i][j][0] = 0.f; acc[i][j][1] = 0.f;
                    acc[i][j][2] = 0.f; acc[i][j][3] = 0.f;
                }
            }
        }
    }

    // ---- store out = sum / R  (fp16) ----
    #pragma unroll
    for (int i = 0; i < 2; i++) {
        int row0 = m0 + m_w + i*16 + (lane >> 2);
        #pragma unroll
        for (int j = 0; j < 4; j++) {
            int col = n_w + j*8 + (lane & 3)*2;
            float p0 = sum[i][j][0]*0.25f, p1 = sum[i][j][1]*0.25f;
            float p2 = sum[i][j][2]*0.25f, p3 = sum[i][j][3]*0.25f;
            if (row0 < NN)
                *reinterpret_cast<uint32_t*>(&Hout[(size_t)row0*128 + col]) = f2h2(p0, p1);
            if (row0 + 8 < NN)
                *reinterpret_cast<uint32_t*>(&Hout[(size_t)(row0+8)*128 + col]) = f2h2(p2, p3);
        }
    }
}

// ---------------- layer-2 GEMM: y2 = h2 @ W2cat (64 cols), fp16 in/out ----------------
// Stage layout: A[128][40] @0 (10240B), B[64][40] @10240 (5120B). Stage = 15360 B.
__global__ __launch_bounds__(256, 2) void gemm2_kernel() {
    constexpr int S = 4;   // 4 K-chunks of 32

    extern __shared__ char dsm[];
    const uint32_t smem_base = smem_u32(dsm);

    const int tid  = threadIdx.x;
    const int lane = tid & 31;
    const int wid  = tid >> 5;
    const int m0   = blockIdx.x * 128;

    const int m_w = (wid >> 1) * 32;
    const int n_w = (wid & 1) * 32;
    const int a_r = lane & 15;
    const int a_c = (lane >> 4) << 3;
    const int b_q = lane >> 3;
    const int b_n = ((b_q >> 1) << 3) + (lane & 7);
    const int b_c = (b_q & 1) << 3;

    auto load_stage = [&](int s) {
        int kc = s & 3;
        uint32_t sb = smem_base + (s % 3) * STAGE_B;
        size_t a_base = (size_t)m0 * 128 + kc * 32;
        size_t b_base = kc * 32;
        #pragma unroll
        for (int i = 0; i < 3; i++) {   // 768 chunks: A 512, B 256
            int g = tid + i * 256;
            if (g < 512) {
                int row = g >> 2, ch = g & 3;
                cp16(sb + row * 80 + ch * 16, g_h2 + a_base + (size_t)row * 128 + ch * 8);
            } else {
                int idx = g - 512, row = idx >> 2, ch = idx & 3;
                cp16(sb + 10240 + row * 80 + ch * 16, g_bt2 + b_base + (size_t)row * 128 + ch * 8);
            }
        }
        CP_COMMIT();
    };

    float sum[2][4][4];
    #pragma unroll
    for (int i = 0; i < 2; i++)
        #pragma unroll
        for (int j = 0; j < 4; j++)
            #pragma unroll
            for (int c = 0; c < 4; c++) sum[i][j][c] = 0.f;

    load_stage(0);
    load_stage(1);

    for (int s = 0; s < S; s++) {
        if (s + 1 < S) CP_WAIT(1); else CP_WAIT(0);
        __syncthreads();
        if (s + 2 < S) load_stage(s + 2);

        uint32_t sb = smem_base + (s % 3) * STAGE_B;
        #pragma unroll
        for (int ks = 0; ks < 2; ks++) {
            int k0 = ks * 16;
            uint32_t a[2][4], b[4][2];
            #pragma unroll
            for (int i = 0; i < 2; i++)
                ldsm4(a[i], sb + (uint32_t)((m_w + i*16 + a_r) * 40 + k0 + a_c) * 2);
            #pragma unroll
            for (int jj = 0; jj < 2; jj++) {
                uint32_t tmp[4];
                ldsm4(tmp, sb + 10240 + (uint32_t)((n_w + jj*16 + b_n) * 40 + k0 + b_c) * 2);
                b[jj*2][0] = tmp[0]; b[jj*2][1] = tmp[1];
                b[jj*2+1][0] = tmp[2]; b[jj*2+1][1] = tmp[3];
            }
            #pragma unroll
            for (int i = 0; i < 2; i++)
                #pragma unroll
                for (int j = 0; j < 4; j++)
                    mma16816(sum[i][j], a[i], b[j]);
        }
    }

    #pragma unroll
    for (int i = 0; i < 2; i++) {
        int row0 = m0 + m_w + i*16 + (lane >> 2);
        #pragma unroll
        for (int j = 0; j < 4; j++) {
            int col = n_w + j*8 + (lane & 3)*2;
            if (row0 < NN)
                *reinterpret_cast<uint32_t*>(&g_y2[(size_t)row0*64 + col]) =
                    f2h2(sum[i][j][0], sum[i][j][1]);
            if (row0 + 8 < NN)
                *reinterpret_cast<uint32_t*>(&g_y2[(size_t)(row0+8)*64 + col]) =
                    f2h2(sum[i][j][2], sum[i][j][3]);
        }
    }
}

// ---------------- layer-2 gather: out[n,c] = 0.25 * sum_r (dsin*sum_e y2[s, r*16+c]*dsout + b2[r,c]) ----------------
__global__ __launch_bounds__(256) void gather2_kernel(const float* __restrict__ b2,
                                                      float* __restrict__ out) {
    int gw   = (blockIdx.x * blockDim.x + threadIdx.x) >> 5;
    int lane = threadIdx.x & 31;
    int node = gw * 2 + (lane >> 4);
    int c    = lane & 15;
    if (node >= NN) return;
    float sum = 0.f;
    #pragma unroll
    for (int r = 0; r < RR; r++) {
        int beg = g_rowptr[r*(NN+1) + node];
        int end = g_rowptr[r*(NN+1) + node + 1];
        float acc = 0.f;
        for (int e = beg; e < end; e++) {
            int2 p = g_csrp[r*EE + e];
            __half v = *reinterpret_cast<const __half*>(&g_y2[(size_t)p.x*64 + r*16 + c]);
            acc = fmaf(__half2float(v), __int_as_float(p.y), acc);
        }
        sum += g_dsin[r*NN + node] * acc + b2[r*16 + c];
    }
    out[node*16 + c] = 0.25f * sum;
}

// ---------------- launch ----------------
extern "C" void kernel_launch(void* const* d_in, const int* in_sizes, int n_in,
                              void* d_out, int out_size) {
    const float* x  = (const float*)d_in[0];
    const float* W0 = (const float*)d_in[1];
    const float* b0 = (const float*)d_in[2];
    const float* W1 = (const float*)d_in[3];
    const float* b1 = (const float*)d_in[4];
    const float* W2 = (const float*)d_in[5];
    const float* b2 = (const float*)d_in[6];
    const int*   src = (const int*)d_in[7];
    const int*   dst = (const int*)d_in[8];
    float* out = (float*)d_out;

    cudaFuncSetAttribute(gemm_kernel<0>, cudaFuncAttributeMaxDynamicSharedMemorySize, GEMM_SMEM);
    cudaFuncSetAttribute(gemm_kernel<1>, cudaFuncAttributeMaxDynamicSharedMemorySize, GEMM_SMEM);
    cudaFuncSetAttribute(gemm2_kernel,   cudaFuncAttributeMaxDynamicSharedMemorySize, GEMM_SMEM);

    // prep (shared by all layers)
    prep_cvt_kernel   <<<(NN*32 + 255)/256, 256>>>(x, W0, W1, W2);
    count_deg_kernel  <<<(RR*EE + 255)/256, 256>>>(src, dst);
    scan_scales_kernel<<<RR, 1024>>>();
    fill_csr_kernel   <<<(RR*EE + 255)/256, 256>>>(src, dst);

    const int GATHER_BLOCKS = (RR*NN*32 + 255) / 256;  // 50000

    // layer 0: gather(x16) -> agg(fp16) ; gemm -> h1 fp16
    gather_kernel<<<GATHER_BLOCKS, 256>>>(1);
    gemm_kernel<0><<<NPAD/64, 256, GEMM_SMEM>>>(b0);
    // layer 1: gather(h1) -> agg ; gemm -> h2 fp16
    gather_kernel<<<GATHER_BLOCKS, 256>>>(0);
    gemm_kernel<1><<<NPAD/64, 256, GEMM_SMEM>>>(b1);
    // layer 2 (GEMM-first): y2 = h2 @ W2cat ; tiny gather with bias+mean
    gemm2_kernel<<<782, 256, GEMM_SMEM>>>();
    gather2_kernel<<<(NN/2*32 + 255)/256, 256>>>(b2, out);
}

// round 15
// speedup vs baseline: 1.3500x; 1.3500x over previous
#include <cuda_runtime.h>
#include <cuda_fp16.h>
#include <cstdint>
#include <cstddef>

// Problem constants
#define NN 100000
#define NPAD 100096   // 1564 * 64
#define EE 400000
#define RR 4
#define NCHUNK 98     // ceil(NN/1024)

// ---------------- scratch (static device globals; no allocation) ----------------
__device__ int   g_deg_in [RR*NN];
__device__ int   g_deg_out[RR*NN];
__device__ int   g_fill   [RR*NN];
__device__ int   g_rowptr [RR*(NN+1)];
__device__ int   g_partial[RR*128];
__device__ __align__(16) int2 g_csrp[RR*EE];   // packed (src, dsout bits)
__device__ float g_dsin   [RR*NN];
__device__ float g_dsout  [RR*NN];
// y2 fp16
__device__ __align__(16) unsigned short g_y2[(size_t)NN*64];
// fp16 feature tables (gather inputs)
__device__ __align__(16) unsigned short g_x16[(size_t)NN*128];
__device__ __align__(16) unsigned short g_h1 [(size_t)NPAD*128];
// aggregated features, fp16: [R][NPAD][128]  (pad rows stay zero)
__device__ __align__(16) unsigned short g_agg[(size_t)RR*NPAD*128];
// layer-1 output, fp16: [NPAD][128]
__device__ __align__(16) unsigned short g_h2[(size_t)NPAD*128];
// transposed fp16 weights: bt[r][n][k] = W[r][k][n]
__device__ __align__(16) unsigned short g_bt0[RR*128*128];
__device__ __align__(16) unsigned short g_bt1[RR*128*128];
__device__ __align__(16) unsigned short g_bt2[64*128];   // [r*16+n][k]

// ---------------- helpers ----------------
__device__ __forceinline__ uint32_t smem_u32(const void* p) {
    uint32_t a;
    asm("{ .reg .u64 t; cvta.to.shared.u64 t, %1; cvt.u32.u64 %0, t; }" : "=r"(a) : "l"(p));
    return a;
}
__device__ __forceinline__ void ldsm4(uint32_t* r, uint32_t addr) {
    asm volatile("ldmatrix.sync.aligned.m8n8.x4.shared.b16 {%0,%1,%2,%3}, [%4];"
                 : "=r"(r[0]), "=r"(r[1]), "=r"(r[2]), "=r"(r[3]) : "r"(addr));
}
__device__ __forceinline__ void mma16816(float* d, const uint32_t* a, const uint32_t* b) {
    asm volatile("mma.sync.aligned.m16n8k16.row.col.f32.f16.f16.f32 "
                 "{%0,%1,%2,%3}, {%4,%5,%6,%7}, {%8,%9}, {%0,%1,%2,%3};"
                 : "+f"(d[0]), "+f"(d[1]), "+f"(d[2]), "+f"(d[3])
                 : "r"(a[0]), "r"(a[1]), "r"(a[2]), "r"(a[3]), "r"(b[0]), "r"(b[1]));
}
__device__ __forceinline__ void cp16(uint32_t dst, const void* src) {
    asm volatile("cp.async.cg.shared.global [%0], [%1], 16;" :: "r"(dst), "l"(src));
}
#define CP_COMMIT() asm volatile("cp.async.commit_group;" ::: "memory")
#define CP_WAIT(n)  asm volatile("cp.async.wait_group " #n ";" ::: "memory")

__device__ __forceinline__ uint32_t f2h2(float a, float b) {   // pack 2 fp32 -> half2 (a=low)
    __half2 h = __floats2half2_rn(a, b);
    return *reinterpret_cast<uint32_t*>(&h);
}
__device__ __forceinline__ unsigned short f2h(float f) {
    __half h = __float2half_rn(f);
    return *reinterpret_cast<unsigned short*>(&h);
}

// ---------------- prep kernels ----------------
// zero counters + convert all weights + convert x -> fp16 (one fused elementwise pass)
__global__ void prep_cvt_kernel(const float* __restrict__ x,
                                const float* __restrict__ W0, const float* __restrict__ W1,
                                const float* __restrict__ W2) {
    int i = blockIdx.x * blockDim.x + threadIdx.x;
    if (i < RR*NN) { g_deg_in[i] = 0; g_deg_out[i] = 0; }
    const int L01 = RR*128*128;   // 65536
    if (i < L01) {
        int r = i >> 14, n = (i >> 7) & 127, k = i & 127;
        g_bt0[i] = f2h(W0[(r<<14) + k*128 + n]);
    } else if (i < 2*L01) {
        int j = i - L01;
        int r = j >> 14, n = (j >> 7) & 127, k = j & 127;
        g_bt1[j] = f2h(W1[(r<<14) + k*128 + n]);
    } else if (i < 2*L01 + 64*128) {
        int j = i - 2*L01;
        int r = j >> 11, n = (j >> 7) & 15, k = j & 127;
        g_bt2[j] = f2h(W2[r*2048 + k*16 + n]);
    }
    if (i < NN*32) {   // one float4 -> one uint2 of half2
        float4 v = reinterpret_cast<const float4*>(x)[i];
        reinterpret_cast<uint2*>(g_x16)[i] = make_uint2(f2h2(v.x, v.y), f2h2(v.z, v.w));
    }
}
__global__ void count_deg_kernel(const int* __restrict__ src, const int* __restrict__ dst) {
    int idx = blockIdx.x * blockDim.x + threadIdx.x;
    if (idx >= RR*EE) return;
    int r = idx / EE;
    atomicAdd(&g_deg_out[r*NN + src[idx]], 1);
    atomicAdd(&g_deg_in [r*NN + dst[idx]], 1);
}
// block-level exclusive scan via warp shuffles (2 barriers)
__global__ void scan1_kernel() {
    __shared__ int wsum[32];
    int r = blockIdx.y, c = blockIdx.x;
    int i = c*1024 + threadIdx.x;
    int lane = threadIdx.x & 31, w = threadIdx.x >> 5;
    int orig = (i < NN) ? g_deg_in[r*NN + i] : 0;
    int v = orig;
    #pragma unroll
    for (int off = 1; off < 32; off <<= 1) {
        int t = __shfl_up_sync(0xffffffff, v, off);
        if (lane >= off) v += t;
    }
    if (lane == 31) wsum[w] = v;
    __syncthreads();
    if (w == 0) {
        int s = wsum[lane];
        #pragma unroll
        for (int off = 1; off < 32; off <<= 1) {
            int t = __shfl_up_sync(0xffffffff, s, off);
            if (lane >= off) s += t;
        }
        wsum[lane] = s;   // inclusive warp-sums
    }
    __syncthreads();
    int base = (w > 0) ? wsum[w-1] : 0;
    if (i < NN) g_rowptr[r*(NN+1) + i] = base + v - orig;      // exclusive
    if (threadIdx.x == 1023) g_partial[r*128 + c] = base + v;  // block total
}
// scan3 with local scan2; also seeds g_fill with the row start (saves a rowptr
// load per edge in fill_csr) and computes degree scales.
__global__ void scan3_scales_kernel() {
    int r = blockIdx.y, c = blockIdx.x;
    __shared__ int base_sh;
    if (threadIdx.x < 32) {
        int lane = threadIdx.x;
        int v = 0;
        for (int j = lane; j < NCHUNK; j += 32)
            if (j < c) v += g_partial[r*128 + j];
        #pragma unroll
        for (int off = 16; off; off >>= 1) v += __shfl_down_sync(0xffffffff, v, off);
        if (lane == 0) base_sh = v;
    }
    __syncthreads();
    int i = c*1024 + threadIdx.x;
    if (i < NN) {
        int rp = g_rowptr[r*(NN+1) + i] + base_sh;
        g_rowptr[r*(NN+1) + i] = rp;
        int ii = r*NN + i;
        g_fill[ii] = rp;   // fill cursor starts at row begin
        g_dsin [ii] = rsqrtf((float)max(g_deg_in [ii], 1));
        g_dsout[ii] = rsqrtf((float)max(g_deg_out[ii], 1));
    }
    if (c == 0 && threadIdx.x == 0) g_rowptr[r*(NN+1) + NN] = EE;
}
// fill packed CSR: single atomic gives the final slot directly
__global__ void fill_csr_kernel(const int* __restrict__ src, const int* __restrict__ dst) {
    int idx = blockIdx.x * blockDim.x + threadIdx.x;
    if (idx >= RR*EE) return;
    int r = idx / EE;
    int s = src[idx];
    int d = dst[idx];
    float w = g_dsout[r*NN + s];
    int pos = atomicAdd(&g_fill[r*NN + d], 1);
    g_csrp[r*EE + pos] = make_int2(s, __float_as_int(w));
}

// ---------------- gather: agg[r][n] = dsin * sum h[s]*dsout[s]  (fp16 in -> fp16 out) ----------------
__global__ __launch_bounds__(256) void gather_kernel(int use_x) {
    int gw   = (blockIdx.x * blockDim.x + threadIdx.x) >> 5;
    int lane = threadIdx.x & 31;
    if (gw >= RR*NN) return;
    int r = gw / NN, n = gw - r*NN;
    const unsigned short* h = use_x ? g_x16 : g_h1;
    int beg = g_rowptr[r*(NN+1) + n];
    int end = g_rowptr[r*(NN+1) + n + 1];
    float4 acc = make_float4(0.f, 0.f, 0.f, 0.f);
    for (int e = beg; e < end; e++) {
        int2 p  = g_csrp[r*EE + e];
        float w = __int_as_float(p.y);
        uint2 q = *reinterpret_cast<const uint2*>(&h[(size_t)p.x*128 + lane*4]);
        float2 f01 = __half22float2(*reinterpret_cast<__half2*>(&q.x));
        float2 f23 = __half22float2(*reinterpret_cast<__half2*>(&q.y));
        acc.x = fmaf(f01.x, w, acc.x);
        acc.y = fmaf(f01.y, w, acc.y);
        acc.z = fmaf(f23.x, w, acc.z);
        acc.w = fmaf(f23.y, w, acc.w);
    }
    float si = g_dsin[r*NN + n];
    size_t off = ((size_t)r*NPAD + n)*128 + lane*4;
    *reinterpret_cast<uint2*>(&g_agg[off]) =
        make_uint2(f2h2(acc.x*si, acc.y*si), f2h2(acc.z*si, acc.w*si));
}

// ---------------- big-layer GEMM: 64x128 tile, fp16 single-pass, 3-stage ring ----------------
// Stage layout: A[64][40] @0 (5120B), B[128][40] @5120 (10240B). Stage = 15360 B.
#define STAGE_B 15360
#define GEMM_SMEM (3*STAGE_B)   // 46080

template<int LAYER>
__global__ __launch_bounds__(256, 2) void gemm_kernel(const float* __restrict__ bias) {
    constexpr int S = 16;   // 4 relations x 4 K-chunks of 32

    const unsigned short* Bt = (LAYER == 0) ? g_bt0 : g_bt1;
    unsigned short* Hout = (LAYER == 0) ? g_h1 : g_h2;

    extern __shared__ char dsm[];
    const uint32_t smem_base = smem_u32(dsm);

    const int tid  = threadIdx.x;
    const int lane = tid & 31;
    const int wid  = tid >> 5;
    const int m0   = blockIdx.x * 64;

    const int m_w = (wid >> 2) * 32;      // 0 or 32
    const int n_w = (wid & 3) * 32;       // 0..96
    const int a_r = lane & 15;
    const int a_c = (lane >> 4) << 3;
    const int b_q = lane >> 3;
    const int b_n = ((b_q >> 1) << 3) + (lane & 7);
    const int b_c = (b_q & 1) << 3;

    auto load_stage = [&](int s) {
        int r = s >> 2, kc = s & 3;
        uint32_t sb = smem_base + (s % 3) * STAGE_B;
        size_t a_base = ((size_t)r * NPAD + m0) * 128 + kc * 32;
        size_t b_base = (size_t)r * 128 * 128 + kc * 32;
        #pragma unroll
        for (int i = 0; i < 3; i++) {   // 768 chunks of 16B
            int g = tid + i * 256;
            if (g < 256) {              // A: 64 rows x 4 chunks
                int row = g >> 2, ch = g & 3;
                cp16(sb + row * 80 + ch * 16, g_agg + a_base + (size_t)row * 128 + ch * 8);
            } else {                    // B: 128 rows x 4 chunks
                int idx = g - 256, row = idx >> 2, ch = idx & 3;
                cp16(sb + 5120 + row * 80 + ch * 16, Bt + b_base + (size_t)row * 128 + ch * 8);
            }
        }
        CP_COMMIT();
    };

    float acc[2][4][4];
    float sum[2][4][4];
    #pragma unroll
    for (int i = 0; i < 2; i++)
        #pragma unroll
        for (int j = 0; j < 4; j++)
            #pragma unroll
            for (int c = 0; c < 4; c++) { acc[i][j][c] = 0.f; sum[i][j][c] = 0.f; }

    load_stage(0);
    load_stage(1);

    for (int s = 0; s < S; s++) {
        if (s + 1 < S) CP_WAIT(1); else CP_WAIT(0);
        __syncthreads();
        if (s + 2 < S) load_stage(s + 2);

        uint32_t sb = smem_base + (s % 3) * STAGE_B;
        #pragma unroll
        for (int ks = 0; ks < 2; ks++) {
            int k0 = ks * 16;
            uint32_t a[2][4], b[4][2];
            #pragma unroll
            for (int i = 0; i < 2; i++)
                ldsm4(a[i], sb + (uint32_t)((m_w + i*16 + a_r) * 40 + k0 + a_c) * 2);
            #pragma unroll
            for (int jj = 0; jj < 2; jj++) {
                uint32_t tmp[4];
                ldsm4(tmp, sb + 5120 + (uint32_t)((n_w + jj*16 + b_n) * 40 + k0 + b_c) * 2);
                b[jj*2][0] = tmp[0]; b[jj*2][1] = tmp[1];
                b[jj*2+1][0] = tmp[2]; b[jj*2+1][1] = tmp[3];
            }
            #pragma unroll
            for (int i = 0; i < 2; i++)
                #pragma unroll
                for (int j = 0; j < 4; j++)
                    mma16816(acc[i][j], a[i], b[j]);
        }

        if ((s & 3) == 3) {   // relation rr done: bias + relu, fold into sum
            int rr = s >> 2;
            #pragma unroll
            for (int i = 0; i < 2; i++) {
                #pragma unroll
                for (int j = 0; j < 4; j++) {
                    int col = n_w + j*8 + (lane & 3)*2;
                    float b0v = bias[rr*128 + col];
                    float b1v = bias[rr*128 + col + 1];
                    sum[i][j][0] += fmaxf(acc[i][j][0] + b0v, 0.f);
                    sum[i][j][1] += fmaxf(acc[i][j][1] + b1v, 0.f);
                    sum[i][j][2] += fmaxf(acc[i][j][2] + b0v, 0.f);
                    sum[i][j][3] += fmaxf(acc[i][j][3] + b1v, 0.f);
                    acc[i][j][0] = 0.f; acc[i][j][1] = 0.f;
                    acc[i][j][2] = 0.f; acc[i][j][3] = 0.f;
                }
            }
        }
    }

    // ---- store out = sum / R  (fp16) ----
    #pragma unroll
    for (int i = 0; i < 2; i++) {
        int row0 = m0 + m_w + i*16 + (lane >> 2);
        #pragma unroll
        for (int j = 0; j < 4; j++) {
            int col = n_w + j*8 + (lane & 3)*2;
            float p0 = sum[i][j][0]*0.25f, p1 = sum[i][j][1]*0.25f;
            float p2 = sum[i][j][2]*0.25f, p3 = sum[i][j][3]*0.25f;
            if (row0 < NN)
                *reinterpret_cast<uint32_t*>(&Hout[(size_t)row0*128 + col]) = f2h2(p0, p1);
            if (row0 + 8 < NN)
                *reinterpret_cast<uint32_t*>(&Hout[(size_t)(row0+8)*128 + col]) = f2h2(p2, p3);
        }
    }
}

// ---------------- layer-2 GEMM: y2 = h2 @ W2cat (64 cols), fp16 in/out ----------------
// Stage layout: A[128][40] @0 (10240B), B[64][40] @10240 (5120B). Stage = 15360 B.
__global__ __launch_bounds__(256, 2) void gemm2_kernel() {
    constexpr int S = 4;   // 4 K-chunks of 32

    extern __shared__ char dsm[];
    const uint32_t smem_base = smem_u32(dsm);

    const int tid  = threadIdx.x;
    const int lane = tid & 31;
    const int wid  = tid >> 5;
    const int m0   = blockIdx.x * 128;

    const int m_w = (wid >> 1) * 32;
    const int n_w = (wid & 1) * 32;
    const int a_r = lane & 15;
    const int a_c = (lane >> 4) << 3;
    const int b_q = lane >> 3;
    const int b_n = ((b_q >> 1) << 3) + (lane & 7);
    const int b_c = (b_q & 1) << 3;

    auto load_stage = [&](int s) {
        int kc = s & 3;
        uint32_t sb = smem_base + (s % 3) * STAGE_B;
        size_t a_base = (size_t)m0 * 128 + kc * 32;
        size_t b_base = kc * 32;
        #pragma unroll
        for (int i = 0; i < 3; i++) {   // 768 chunks: A 512, B 256
            int g = tid + i * 256;
            if (g < 512) {
                int row = g >> 2, ch = g & 3;
                cp16(sb + row * 80 + ch * 16, g_h2 + a_base + (size_t)row * 128 + ch * 8);
            } else {
                int idx = g - 512, row = idx >> 2, ch = idx & 3;
                cp16(sb + 10240 + row * 80 + ch * 16, g_bt2 + b_base + (size_t)row * 128 + ch * 8);
            }
        }
        CP_COMMIT();
    };

    float sum[2][4][4];
    #pragma unroll
    for (int i = 0; i < 2; i++)
        #pragma unroll
        for (int j = 0; j < 4; j++)
            #pragma unroll
            for (int c = 0; c < 4; c++) sum[i][j][c] = 0.f;

    load_stage(0);
    load_stage(1);

    for (int s = 0; s < S; s++) {
        if (s + 1 < S) CP_WAIT(1); else CP_WAIT(0);
        __syncthreads();
        if (s + 2 < S) load_stage(s + 2);

        uint32_t sb = smem_base + (s % 3) * STAGE_B;
        #pragma unroll
        for (int ks = 0; ks < 2; ks++) {
            int k0 = ks * 16;
            uint32_t a[2][4], b[4][2];
            #pragma unroll
            for (int i = 0; i < 2; i++)
                ldsm4(a[i], sb + (uint32_t)((m_w + i*16 + a_r) * 40 + k0 + a_c) * 2);
            #pragma unroll
            for (int jj = 0; jj < 2; jj++) {
                uint32_t tmp[4];
                ldsm4(tmp, sb + 10240 + (uint32_t)((n_w + jj*16 + b_n) * 40 + k0 + b_c) * 2);
                b[jj*2][0] = tmp[0]; b[jj*2][1] = tmp[1];
                b[jj*2+1][0] = tmp[2]; b[jj*2+1][1] = tmp[3];
            }
            #pragma unroll
            for (int i = 0; i < 2; i++)
                #pragma unroll
                for (int j = 0; j < 4; j++)
                    mma16816(sum[i][j], a[i], b[j]);
        }
    }

    #pragma unroll
    for (int i = 0; i < 2; i++) {
        int row0 = m0 + m_w + i*16 + (lane >> 2);
        #pragma unroll
        for (int j = 0; j < 4; j++) {
            int col = n_w + j*8 + (lane & 3)*2;
            if (row0 < NN)
                *reinterpret_cast<uint32_t*>(&g_y2[(size_t)row0*64 + col]) =
                    f2h2(sum[i][j][0], sum[i][j][1]);
            if (row0 + 8 < NN)
                *reinterpret_cast<uint32_t*>(&g_y2[(size_t)(row0+8)*64 + col]) =
                    f2h2(sum[i][j][2], sum[i][j][3]);
        }
    }
}

// ---------------- layer-2 gather: out[n,c] = 0.25 * sum_r (dsin*sum_e y2[s, r*16+c]*dsout + b2[r,c]) ----------------
__global__ __launch_bounds__(256) void gather2_kernel(const float* __restrict__ b2,
                                                      float* __restrict__ out) {
    int gw   = (blockIdx.x * blockDim.x + threadIdx.x) >> 5;
    int lane = threadIdx.x & 31;
    int node = gw * 2 + (lane >> 4);
    int c    = lane & 15;
    if (node >= NN) return;
    float sum = 0.f;
    #pragma unroll
    for (int r = 0; r < RR; r++) {
        int beg = g_rowptr[r*(NN+1) + node];
        int end = g_rowptr[r*(NN+1) + node + 1];
        float acc = 0.f;
        for (int e = beg; e < end; e++) {
            int2 p = g_csrp[r*EE + e];
            __half v = *reinterpret_cast<const __half*>(&g_y2[(size_t)p.x*64 + r*16 + c]);
            acc = fmaf(__half2float(v), __int_as_float(p.y), acc);
        }
        sum += g_dsin[r*NN + node] * acc + b2[r*16 + c];
    }
    out[node*16 + c] = 0.25f * sum;
}

// ---------------- launch ----------------
extern "C" void kernel_launch(void* const* d_in, const int* in_sizes, int n_in,
                              void* d_out, int out_size) {
    const float* x  = (const float*)d_in[0];
    const float* W0 = (const float*)d_in[1];
    const float* b0 = (const float*)d_in[2];
    const float* W1 = (const float*)d_in[3];
    const float* b1 = (const float*)d_in[4];
    const float* W2 = (const float*)d_in[5];
    const float* b2 = (const float*)d_in[6];
    const int*   src = (const int*)d_in[7];
    const int*   dst = (const int*)d_in[8];
    float* out = (float*)d_out;

    cudaFuncSetAttribute(gemm_kernel<0>, cudaFuncAttributeMaxDynamicSharedMemorySize, GEMM_SMEM);
    cudaFuncSetAttribute(gemm_kernel<1>, cudaFuncAttributeMaxDynamicSharedMemorySize, GEMM_SMEM);
    cudaFuncSetAttribute(gemm2_kernel,   cudaFuncAttributeMaxDynamicSharedMemorySize, GEMM_SMEM);

    // prep (shared by all layers)
    prep_cvt_kernel   <<<(NN*32 + 255)/256, 256>>>(x, W0, W1, W2);
    count_deg_kernel  <<<(RR*EE + 255)/256, 256>>>(src, dst);
    scan1_kernel      <<<dim3(NCHUNK, RR), 1024>>>();
    scan3_scales_kernel<<<dim3(NCHUNK, RR), 1024>>>();
    fill_csr_kernel   <<<(RR*EE + 255)/256, 256>>>(src, dst);

    const int GATHER_BLOCKS = (RR*NN*32 + 255) / 256;  // 50000

    // layer 0: gather(x16) -> agg(fp16) ; gemm -> h1 fp16
    gather_kernel<<<GATHER_BLOCKS, 256>>>(1);
    gemm_kernel<0><<<NPAD/64, 256, GEMM_SMEM>>>(b0);
    // layer 1: gather(h1) -> agg ; gemm -> h2 fp16
    gather_kernel<<<GATHER_BLOCKS, 256>>>(0);
    gemm_kernel<1><<<NPAD/64, 256, GEMM_SMEM>>>(b1);
    // layer 2 (GEMM-first): y2 = h2 @ W2cat ; tiny gather with bias+mean
    gemm2_kernel<<<782, 256, GEMM_SMEM>>>();
    gather2_kernel<<<(NN/2*32 + 255)/256, 256>>>(b2, out);
}

// round 16
// speedup vs baseline: 1.4153x; 1.0484x over previous
#include <cuda_runtime.h>
#include <cuda_fp16.h>
#include <cstdint>
#include <cstddef>

// Problem constants
#define NN 100000
#define NPAD 100096   // 1564 * 64
#define EE 400000
#define RR 4
#define NCHUNK 98     // ceil(NN/1024)

// ---------------- scratch (static device globals; no allocation) ----------------
__device__ int   g_deg_in [RR*NN];
__device__ int   g_deg_out[RR*NN];
__device__ int   g_fill   [RR*NN];
__device__ int   g_rowptr [RR*(NN+1)];
__device__ int   g_partial[RR*128];
__device__ __align__(16) int2 g_csrp[RR*EE];   // packed (src, dsout bits)
__device__ float g_dsin   [RR*NN];
__device__ float g_dsout  [RR*NN];
// y2 fp16
__device__ __align__(16) unsigned short g_y2[(size_t)NN*64];
// fp16 feature tables (gather inputs)
__device__ __align__(16) unsigned short g_x16[(size_t)NN*128];
__device__ __align__(16) unsigned short g_h1 [(size_t)NPAD*128];
// aggregated features, fp16: [R][NPAD][128]  (pad rows stay zero)
__device__ __align__(16) unsigned short g_agg[(size_t)RR*NPAD*128];
// layer-1 output, fp16: [NPAD][128]
__device__ __align__(16) unsigned short g_h2[(size_t)NPAD*128];
// transposed fp16 weights: bt[r][n][k] = W[r][k][n]
__device__ __align__(16) unsigned short g_bt0[RR*128*128];
__device__ __align__(16) unsigned short g_bt1[RR*128*128];
__device__ __align__(16) unsigned short g_bt2[64*128];   // [r*16+n][k]

// ---------------- helpers ----------------
__device__ __forceinline__ uint32_t smem_u32(const void* p) {
    uint32_t a;
    asm("{ .reg .u64 t; cvta.to.shared.u64 t, %1; cvt.u32.u64 %0, t; }" : "=r"(a) : "l"(p));
    return a;
}
__device__ __forceinline__ void ldsm4(uint32_t* r, uint32_t addr) {
    asm volatile("ldmatrix.sync.aligned.m8n8.x4.shared.b16 {%0,%1,%2,%3}, [%4];"
                 : "=r"(r[0]), "=r"(r[1]), "=r"(r[2]), "=r"(r[3]) : "r"(addr));
}
__device__ __forceinline__ void mma16816(float* d, const uint32_t* a, const uint32_t* b) {
    asm volatile("mma.sync.aligned.m16n8k16.row.col.f32.f16.f16.f32 "
                 "{%0,%1,%2,%3}, {%4,%5,%6,%7}, {%8,%9}, {%0,%1,%2,%3};"
                 : "+f"(d[0]), "+f"(d[1]), "+f"(d[2]), "+f"(d[3])
                 : "r"(a[0]), "r"(a[1]), "r"(a[2]), "r"(a[3]), "r"(b[0]), "r"(b[1]));
}
__device__ __forceinline__ void cp16(uint32_t dst, const void* src) {
    asm volatile("cp.async.cg.shared.global [%0], [%1], 16;" :: "r"(dst), "l"(src));
}
#define CP_COMMIT() asm volatile("cp.async.commit_group;" ::: "memory")
#define CP_WAIT(n)  asm volatile("cp.async.wait_group " #n ";" ::: "memory")

__device__ __forceinline__ uint32_t f2h2(float a, float b) {   // pack 2 fp32 -> half2 (a=low)
    __half2 h = __floats2half2_rn(a, b);
    return *reinterpret_cast<uint32_t*>(&h);
}
__device__ __forceinline__ unsigned short f2h(float f) {
    __half h = __float2half_rn(f);
    return *reinterpret_cast<unsigned short*>(&h);
}

// ---------------- prep kernels ----------------
// zero counters + convert all weights + convert x -> fp16 (one fused elementwise pass)
__global__ void prep_cvt_kernel(const float* __restrict__ x,
                                const float* __restrict__ W0, const float* __restrict__ W1,
                                const float* __restrict__ W2) {
    int i = blockIdx.x * blockDim.x + threadIdx.x;
    if (i < RR*NN) { g_deg_in[i] = 0; g_deg_out[i] = 0; }
    const int L01 = RR*128*128;   // 65536
    if (i < L01) {
        int r = i >> 14, n = (i >> 7) & 127, k = i & 127;
        g_bt0[i] = f2h(W0[(r<<14) + k*128 + n]);
    } else if (i < 2*L01) {
        int j = i - L01;
        int r = j >> 14, n = (j >> 7) & 127, k = j & 127;
        g_bt1[j] = f2h(W1[(r<<14) + k*128 + n]);
    } else if (i < 2*L01 + 64*128) {
        int j = i - 2*L01;
        int r = j >> 11, n = (j >> 7) & 15, k = j & 127;
        g_bt2[j] = f2h(W2[r*2048 + k*16 + n]);
    }
    if (i < NN*32) {   // one float4 -> one uint2 of half2
        float4 v = reinterpret_cast<const float4*>(x)[i];
        reinterpret_cast<uint2*>(g_x16)[i] = make_uint2(f2h2(v.x, v.y), f2h2(v.z, v.w));
    }
}
__global__ void count_deg_kernel(const int* __restrict__ src, const int* __restrict__ dst) {
    int idx = blockIdx.x * blockDim.x + threadIdx.x;
    if (idx >= RR*EE) return;
    int r = idx / EE;
    atomicAdd(&g_deg_out[r*NN + src[idx]], 1);
    atomicAdd(&g_deg_in [r*NN + dst[idx]], 1);
}
// block-level exclusive scan via warp shuffles (2 barriers)
__global__ void scan1_kernel() {
    __shared__ int wsum[32];
    int r = blockIdx.y, c = blockIdx.x;
    int i = c*1024 + threadIdx.x;
    int lane = threadIdx.x & 31, w = threadIdx.x >> 5;
    int orig = (i < NN) ? g_deg_in[r*NN + i] : 0;
    int v = orig;
    #pragma unroll
    for (int off = 1; off < 32; off <<= 1) {
        int t = __shfl_up_sync(0xffffffff, v, off);
        if (lane >= off) v += t;
    }
    if (lane == 31) wsum[w] = v;
    __syncthreads();
    if (w == 0) {
        int s = wsum[lane];
        #pragma unroll
        for (int off = 1; off < 32; off <<= 1) {
            int t = __shfl_up_sync(0xffffffff, s, off);
            if (lane >= off) s += t;
        }
        wsum[lane] = s;   // inclusive warp-sums
    }
    __syncthreads();
    int base = (w > 0) ? wsum[w-1] : 0;
    if (i < NN) g_rowptr[r*(NN+1) + i] = base + v - orig;      // exclusive
    if (threadIdx.x == 1023) g_partial[r*128 + c] = base + v;  // block total
}
// scan3 with local scan2; also seeds g_fill with the row start (saves a rowptr
// load per edge in fill_csr) and computes degree scales.
__global__ void scan3_scales_kernel() {
    int r = blockIdx.y, c = blockIdx.x;
    __shared__ int base_sh;
    if (threadIdx.x < 32) {
        int lane = threadIdx.x;
        int v = 0;
        for (int j = lane; j < NCHUNK; j += 32)
            if (j < c) v += g_partial[r*128 + j];
        #pragma unroll
        for (int off = 16; off; off >>= 1) v += __shfl_down_sync(0xffffffff, v, off);
        if (lane == 0) base_sh = v;
    }
    __syncthreads();
    int i = c*1024 + threadIdx.x;
    if (i < NN) {
        int rp = g_rowptr[r*(NN+1) + i] + base_sh;
        g_rowptr[r*(NN+1) + i] = rp;
        int ii = r*NN + i;
        g_fill[ii] = rp;   // fill cursor starts at row begin
        g_dsin [ii] = rsqrtf((float)max(g_deg_in [ii], 1));
        g_dsout[ii] = rsqrtf((float)max(g_deg_out[ii], 1));
    }
    if (c == 0 && threadIdx.x == 0) g_rowptr[r*(NN+1) + NN] = EE;
}
// fill packed CSR: single atomic gives the final slot directly
__global__ void fill_csr_kernel(const int* __restrict__ src, const int* __restrict__ dst) {
    int idx = blockIdx.x * blockDim.x + threadIdx.x;
    if (idx >= RR*EE) return;
    int r = idx / EE;
    int s = src[idx];
    int d = dst[idx];
    float w = g_dsout[r*NN + s];
    int pos = atomicAdd(&g_fill[r*NN + d], 1);
    g_csrp[r*EE + pos] = make_int2(s, __float_as_int(w));
}

// ---------------- gather: agg[r][n] = dsin * sum h[s]*dsout[s]  (fp16 in -> fp16 out) ----------------
__global__ __launch_bounds__(256) void gather_kernel(int use_x) {
    int gw   = (blockIdx.x * blockDim.x + threadIdx.x) >> 5;
    int lane = threadIdx.x & 31;
    if (gw >= RR*NN) return;
    int r = gw / NN, n = gw - r*NN;
    const unsigned short* h = use_x ? g_x16 : g_h1;
    int beg = g_rowptr[r*(NN+1) + n];
    int end = g_rowptr[r*(NN+1) + n + 1];
    float4 acc = make_float4(0.f, 0.f, 0.f, 0.f);
    for (int e = beg; e < end; e++) {
        int2 p  = g_csrp[r*EE + e];
        float w = __int_as_float(p.y);
        uint2 q = *reinterpret_cast<const uint2*>(&h[(size_t)p.x*128 + lane*4]);
        float2 f01 = __half22float2(*reinterpret_cast<__half2*>(&q.x));
        float2 f23 = __half22float2(*reinterpret_cast<__half2*>(&q.y));
        acc.x = fmaf(f01.x, w, acc.x);
        acc.y = fmaf(f01.y, w, acc.y);
        acc.z = fmaf(f23.x, w, acc.z);
        acc.w = fmaf(f23.y, w, acc.w);
    }
    float si = g_dsin[r*NN + n];
    size_t off = ((size_t)r*NPAD + n)*128 + lane*4;
    *reinterpret_cast<uint2*>(&g_agg[off]) =
        make_uint2(f2h2(acc.x*si, acc.y*si), f2h2(acc.z*si, acc.w*si));
}

// ---------------- big-layer GEMM: 64x128 tile, fp16, K-chunk 64, 3-stage ring ----------------
// Stage layout: A[64][72] @0 (9216B), B[128][72] @9216 (18432B). Stage = 27648 B.
#define STAGE_B 27648
#define GEMM_SMEM (3*STAGE_B)   // 82944

template<int LAYER>
__global__ __launch_bounds__(256, 2) void gemm_kernel(const float* __restrict__ bias) {
    constexpr int S = 8;   // 4 relations x 2 K-chunks of 64

    const unsigned short* Bt = (LAYER == 0) ? g_bt0 : g_bt1;
    unsigned short* Hout = (LAYER == 0) ? g_h1 : g_h2;

    extern __shared__ char dsm[];
    const uint32_t smem_base = smem_u32(dsm);

    const int tid  = threadIdx.x;
    const int lane = tid & 31;
    const int wid  = tid >> 5;
    const int m0   = blockIdx.x * 64;

    const int m_w = (wid >> 2) * 32;      // 0 or 32
    const int n_w = (wid & 3) * 32;       // 0..96
    const int a_r = lane & 15;
    const int a_c = (lane >> 4) << 3;
    const int b_q = lane >> 3;
    const int b_n = ((b_q >> 1) << 3) + (lane & 7);
    const int b_c = (b_q & 1) << 3;

    auto load_stage = [&](int s) {
        int r = s >> 1, kc = s & 1;
        uint32_t sb = smem_base + (s % 3) * STAGE_B;
        size_t a_base = ((size_t)r * NPAD + m0) * 128 + kc * 64;
        size_t b_base = (size_t)r * 128 * 128 + kc * 64;
        #pragma unroll
        for (int i = 0; i < 6; i++) {   // 1536 chunks of 16B
            int g = tid + i * 256;
            if (g < 512) {              // A: 64 rows x 8 chunks
                int row = g >> 3, ch = g & 7;
                cp16(sb + row * 144 + ch * 16, g_agg + a_base + (size_t)row * 128 + ch * 8);
            } else {                    // B: 128 rows x 8 chunks
                int idx = g - 512, row = idx >> 3, ch = idx & 7;
                cp16(sb + 9216 + row * 144 + ch * 16, Bt + b_base + (size_t)row * 128 + ch * 8);
            }
        }
        CP_COMMIT();
    };

    float acc[2][4][4];
    float sum[2][4][4];
    #pragma unroll
    for (int i = 0; i < 2; i++)
        #pragma unroll
        for (int j = 0; j < 4; j++)
            #pragma unroll
            for (int c = 0; c < 4; c++) { acc[i][j][c] = 0.f; sum[i][j][c] = 0.f; }

    load_stage(0);
    load_stage(1);

    for (int s = 0; s < S; s++) {
        if (s + 1 < S) CP_WAIT(1); else CP_WAIT(0);
        __syncthreads();
        if (s + 2 < S) load_stage(s + 2);

        uint32_t sb = smem_base + (s % 3) * STAGE_B;
        #pragma unroll
        for (int ks = 0; ks < 4; ks++) {
            int k0 = ks * 16;
            uint32_t a[2][4], b[4][2];
            #pragma unroll
            for (int i = 0; i < 2; i++)
                ldsm4(a[i], sb + (uint32_t)((m_w + i*16 + a_r) * 72 + k0 + a_c) * 2);
            #pragma unroll
            for (int jj = 0; jj < 2; jj++) {
                uint32_t tmp[4];
                ldsm4(tmp, sb + 9216 + (uint32_t)((n_w + jj*16 + b_n) * 72 + k0 + b_c) * 2);
                b[jj*2][0] = tmp[0]; b[jj*2][1] = tmp[1];
                b[jj*2+1][0] = tmp[2]; b[jj*2+1][1] = tmp[3];
            }
            #pragma unroll
            for (int i = 0; i < 2; i++)
                #pragma unroll
                for (int j = 0; j < 4; j++)
                    mma16816(acc[i][j], a[i], b[j]);
        }

        if (s & 1) {   // relation rr done: bias + relu, fold into sum
            int rr = s >> 1;
            #pragma unroll
            for (int i = 0; i < 2; i++) {
                #pragma unroll
                for (int j = 0; j < 4; j++) {
                    int col = n_w + j*8 + (lane & 3)*2;
                    float b0v = bias[rr*128 + col];
                    float b1v = bias[rr*128 + col + 1];
                    sum[i][j][0] += fmaxf(acc[i][j][0] + b0v, 0.f);
                    sum[i][j][1] += fmaxf(acc[i][j][1] + b1v, 0.f);
                    sum[i][j][2] += fmaxf(acc[i][j][2] + b0v, 0.f);
                    sum[i][j][3] += fmaxf(acc[i][j][3] + b1v, 0.f);
                    acc[i][j][0] = 0.f; acc[i][j][1] = 0.f;
                    acc[i][j][2] = 0.f; acc[i][j][3] = 0.f;
                }
            }
        }
    }

    // ---- store out = sum / R  (fp16) ----
    #pragma unroll
    for (int i = 0; i < 2; i++) {
        int row0 = m0 + m_w + i*16 + (lane >> 2);
        #pragma unroll
        for (int j = 0; j < 4; j++) {
            int col = n_w + j*8 + (lane & 3)*2;
            float p0 = sum[i][j][0]*0.25f, p1 = sum[i][j][1]*0.25f;
            float p2 = sum[i][j][2]*0.25f, p3 = sum[i][j][3]*0.25f;
            if (row0 < NN)
                *reinterpret_cast<uint32_t*>(&Hout[(size_t)row0*128 + col]) = f2h2(p0, p1);
            if (row0 + 8 < NN)
                *reinterpret_cast<uint32_t*>(&Hout[(size_t)(row0+8)*128 + col]) = f2h2(p2, p3);
        }
    }
}

// ---------------- layer-2 GEMM: y2 = h2 @ W2cat (64 cols), fp16, K-chunk 64 ----------------
// Stage layout: A[128][72] @0 (18432B), B[64][72] @18432 (9216B). Stage = 27648 B.
__global__ __launch_bounds__(256, 2) void gemm2_kernel() {
    constexpr int S = 2;   // 2 K-chunks of 64

    extern __shared__ char dsm[];
    const uint32_t smem_base = smem_u32(dsm);

    const int tid  = threadIdx.x;
    const int lane = tid & 31;
    const int wid  = tid >> 5;
    const int m0   = blockIdx.x * 128;

    const int m_w = (wid >> 1) * 32;
    const int n_w = (wid & 1) * 32;
    const int a_r = lane & 15;
    const int a_c = (lane >> 4) << 3;
    const int b_q = lane >> 3;
    const int b_n = ((b_q >> 1) << 3) + (lane & 7);
    const int b_c = (b_q & 1) << 3;

    auto load_stage = [&](int s) {
        int kc = s;
        uint32_t sb = smem_base + (s % 3) * STAGE_B;
        size_t a_base = (size_t)m0 * 128 + kc * 64;
        size_t b_base = kc * 64;
        #pragma unroll
        for (int i = 0; i < 6; i++) {   // 1536 chunks: A 1024, B 512
            int g = tid + i * 256;
            if (g < 1024) {
                int row = g >> 3, ch = g & 7;
                cp16(sb + row * 144 + ch * 16, g_h2 + a_base + (size_t)row * 128 + ch * 8);
            } else {
                int idx = g - 1024, row = idx >> 3, ch = idx & 7;
                cp16(sb + 18432 + row * 144 + ch * 16, g_bt2 + b_base + (size_t)row * 128 + ch * 8);
            }
        }
        CP_COMMIT();
    };

    float sum[2][4][4];
    #pragma unroll
    for (int i = 0; i < 2; i++)
        #pragma unroll
        for (int j = 0; j < 4; j++)
            #pragma unroll
            for (int c = 0; c < 4; c++) sum[i][j][c] = 0.f;

    load_stage(0);
    load_stage(1);

    for (int s = 0; s < S; s++) {
        if (s + 1 < S) CP_WAIT(1); else CP_WAIT(0);
        __syncthreads();

        uint32_t sb = smem_base + (s % 3) * STAGE_B;
        #pragma unroll
        for (int ks = 0; ks < 4; ks++) {
            int k0 = ks * 16;
            uint32_t a[2][4], b[4][2];
            #pragma unroll
            for (int i = 0; i < 2; i++)
                ldsm4(a[i], sb + (uint32_t)((m_w + i*16 + a_r) * 72 + k0 + a_c) * 2);
            #pragma unroll
            for (int jj = 0; jj < 2; jj++) {
                uint32_t tmp[4];
                ldsm4(tmp, sb + 18432 + (uint32_t)((n_w + jj*16 + b_n) * 72 + k0 + b_c) * 2);
                b[jj*2][0] = tmp[0]; b[jj*2][1] = tmp[1];
                b[jj*2+1][0] = tmp[2]; b[jj*2+1][1] = tmp[3];
            }
            #pragma unroll
            for (int i = 0; i < 2; i++)
                #pragma unroll
                for (int j = 0; j < 4; j++)
                    mma16816(sum[i][j], a[i], b[j]);
        }
    }

    #pragma unroll
    for (int i = 0; i < 2; i++) {
        int row0 = m0 + m_w + i*16 + (lane >> 2);
        #pragma unroll
        for (int j = 0; j < 4; j++) {
            int col = n_w + j*8 + (lane & 3)*2;
            if (row0 < NN)
                *reinterpret_cast<uint32_t*>(&g_y2[(size_t)row0*64 + col]) =
                    f2h2(sum[i][j][0], sum[i][j][1]);
            if (row0 + 8 < NN)
                *reinterpret_cast<uint32_t*>(&g_y2[(size_t)(row0+8)*64 + col]) =
                    f2h2(sum[i][j][2], sum[i][j][3]);
        }
    }
}

// ---------------- layer-2 gather: out[n,c] = 0.25 * sum_r (dsin*sum_e y2[s, r*16+c]*dsout + b2[r,c]) ----------------
__global__ __launch_bounds__(256) void gather2_kernel(const float* __restrict__ b2,
                                                      float* __restrict__ out) {
    int gw   = (blockIdx.x * blockDim.x + threadIdx.x) >> 5;
    int lane = threadIdx.x & 31;
    int node = gw * 2 + (lane >> 4);
    int c    = lane & 15;
    if (node >= NN) return;
    float sum = 0.f;
    #pragma unroll
    for (int r = 0; r < RR; r++) {
        int beg = g_rowptr[r*(NN+1) + node];
        int end = g_rowptr[r*(NN+1) + node + 1];
        float acc = 0.f;
        for (int e = beg; e < end; e++) {
            int2 p = g_csrp[r*EE + e];
            __half v = *reinterpret_cast<const __half*>(&g_y2[(size_t)p.x*64 + r*16 + c]);
            acc = fmaf(__half2float(v), __int_as_float(p.y), acc);
        }
        sum += g_dsin[r*NN + node] * acc + b2[r*16 + c];
    }
    out[node*16 + c] = 0.25f * sum;
}

// ---------------- launch ----------------
extern "C" void kernel_launch(void* const* d_in, const int* in_sizes, int n_in,
                              void* d_out, int out_size) {
    const float* x  = (const float*)d_in[0];
    const float* W0 = (const float*)d_in[1];
    const float* b0 = (const float*)d_in[2];
    const float* W1 = (const float*)d_in[3];
    const float* b1 = (const float*)d_in[4];
    const float* W2 = (const float*)d_in[5];
    const float* b2 = (const float*)d_in[6];
    const int*   src = (const int*)d_in[7];
    const int*   dst = (const int*)d_in[8];
    float* out = (float*)d_out;

    cudaFuncSetAttribute(gemm_kernel<0>, cudaFuncAttributeMaxDynamicSharedMemorySize, GEMM_SMEM);
    cudaFuncSetAttribute(gemm_kernel<1>, cudaFuncAttributeMaxDynamicSharedMemorySize, GEMM_SMEM);
    cudaFuncSetAttribute(gemm2_kernel,   cudaFuncAttributeMaxDynamicSharedMemorySize, GEMM_SMEM);

    // prep (shared by all layers)
    prep_cvt_kernel   <<<(NN*32 + 255)/256, 256>>>(x, W0, W1, W2);
    count_deg_kernel  <<<(RR*EE + 255)/256, 256>>>(src, dst);
    scan1_kernel      <<<dim3(NCHUNK, RR), 1024>>>();
    scan3_scales_kernel<<<dim3(NCHUNK, RR), 1024>>>();
    fill_csr_kernel   <<<(RR*EE + 255)/256, 256>>>(src, dst);

    const int GATHER_BLOCKS = (RR*NN*32 + 255) / 256;  // 50000

    // layer 0: gather(x16) -> agg(fp16) ; gemm -> h1 fp16
    gather_kernel<<<GATHER_BLOCKS, 256>>>(1);
    gemm_kernel<0><<<NPAD/64, 256, GEMM_SMEM>>>(b0);
    // layer 1: gather(h1) -> agg ; gemm -> h2 fp16
    gather_kernel<<<GATHER_BLOCKS, 256>>>(0);
    gemm_kernel<1><<<NPAD/64, 256, GEMM_SMEM>>>(b1);
    // layer 2 (GEMM-first): y2 = h2 @ W2cat ; tiny gather with bias+mean
    gemm2_kernel<<<782, 256, GEMM_SMEM>>>();
    gather2_kernel<<<(NN/2*32 + 255)/256, 256>>>(b2, out);
}